// round 4
// baseline (speedup 1.0000x reference)
#include <cuda_runtime.h>
#include <cuda_bf16.h>

// Problem constants
#define BATCH   4096
#define NOBST   128
#define VEH     18        // 2*6 + 6
#define OBD     4
#define F1      22        // VEH + OBD
#define H       256
#define OBSF    138
#define COMBF   396       // 138 + 256 + 2
#define TN      32        // obstacle tile
#define H1PAD   36        // padded row (multiple of 4 -> 16B aligned float4 rows)

__global__ __launch_bounds__(256)
void setq_fused_kernel(const float* __restrict__ obs,
                       const float* __restrict__ obstacles,
                       const float* __restrict__ act,
                       const float* __restrict__ ow1,
                       const float* __restrict__ ob1,
                       const float* __restrict__ ow2,
                       const float* __restrict__ ob2,
                       const float* __restrict__ qw1,
                       const float* __restrict__ qb1,
                       const float* __restrict__ qw2,
                       const float* __restrict__ qb2,
                       const float* __restrict__ qw3,
                       const float* __restrict__ qb3,
                       float* __restrict__ out)
{
    const int b = blockIdx.x;
    const int t = threadIdx.x;          // hidden channel 0..255

    __shared__ float obss[OBSF];        // full obs row (veh = obss[0..17])
    __shared__ float acts[2];
    __shared__ float masks[NOBST];
    __shared__ float obsts[OBD][TN];    // obstacle features for current tile
    __shared__ float h1s[H * H1PAD];    // h1 tile, layout [k][j], padded
    __shared__ float pooled[H];
    __shared__ float q1s[H];
    __shared__ float wsum[8];

    // ---- stage per-batch scalars ----
    if (t < OBSF)  obss[t]  = obs[b * OBSF + t];
    if (t < NOBST) masks[t] = obstacles[(b * 5 + 4) * NOBST + t];
    if (t < 2)     acts[t]  = act[b * 2 + t];
    __syncthreads();

    // ---- hoisted vehicle contribution to h1 channel t ----
    float base = ob1[t];
    #pragma unroll
    for (int f = 0; f < VEH; f++)
        base = fmaf(obss[f], ow1[f * H + t], base);
    const float w18 = ow1[(VEH + 0) * H + t];
    const float w19 = ow1[(VEH + 1) * H + t];
    const float w20 = ow1[(VEH + 2) * H + t];
    const float w21 = ow1[(VEH + 3) * H + t];
    const float ob2t = ob2[t];

    float pool = 0.f;

    // ---- obstacle MLP over 4 tiles of 32 ----
    for (int tile = 0; tile < NOBST / TN; tile++) {
        const int n0 = tile * TN;
        __syncthreads();   // previous tile's h1s reads done
        if (t < OBD * TN)
            obsts[t / TN][t % TN] =
                obstacles[(b * 5 + (t / TN)) * NOBST + n0 + (t % TN)];
        __syncthreads();

        // h1[t][j] for this tile: base + 4 obstacle-feature FMAs, relu
        #pragma unroll
        for (int j = 0; j < TN; j++) {
            float v = base;
            v = fmaf(w18, obsts[0][j], v);
            v = fmaf(w19, obsts[1][j], v);
            v = fmaf(w20, obsts[2][j], v);
            v = fmaf(w21, obsts[3][j], v);
            h1s[t * H1PAD + j] = fmaxf(v, 0.f);
        }
        __syncthreads();

        // h2 accumulation: acc[j] = sum_k h1[k][j] * ow2[k][t]
        float acc[TN];
        #pragma unroll
        for (int j = 0; j < TN; j++) acc[j] = 0.f;

        #pragma unroll 2
        for (int k = 0; k < H; k++) {
            const float w = ow2[k * H + t];               // coalesced, L1/L2 hit
            const float4* row = (const float4*)(h1s + k * H1PAD); // broadcast
            #pragma unroll
            for (int q = 0; q < 8; q++) {
                float4 a = row[q];
                acc[4 * q + 0] = fmaf(a.x, w, acc[4 * q + 0]);
                acc[4 * q + 1] = fmaf(a.y, w, acc[4 * q + 1]);
                acc[4 * q + 2] = fmaf(a.z, w, acc[4 * q + 2]);
                acc[4 * q + 3] = fmaf(a.w, w, acc[4 * q + 3]);
            }
        }

        // fused bias + relu + masked pooling (h2 never materialized)
        #pragma unroll
        for (int j = 0; j < TN; j++) {
            float h2 = fmaxf(acc[j] + ob2t, 0.f);
            pool = fmaf(masks[n0 + j], h2, pool);
        }
    }

    pooled[t] = pool;
    __syncthreads();

    // ---- Q head: q1 = relu(comb @ qw1 + qb1) ----
    float a1 = qb1[t];
    #pragma unroll 4
    for (int f = 0; f < OBSF; f++)
        a1 = fmaf(obss[f], qw1[f * H + t], a1);
    #pragma unroll 4
    for (int f = 0; f < H; f++)
        a1 = fmaf(pooled[f], qw1[(OBSF + f) * H + t], a1);
    a1 = fmaf(acts[0], qw1[(OBSF + H + 0) * H + t], a1);
    a1 = fmaf(acts[1], qw1[(OBSF + H + 1) * H + t], a1);
    q1s[t] = fmaxf(a1, 0.f);
    __syncthreads();

    // ---- q2 = relu(q1 @ qw2 + qb2) ----
    float a2 = qb2[t];
    #pragma unroll 4
    for (int k = 0; k < H; k++)
        a2 = fmaf(q1s[k], qw2[k * H + t], a2);
    a2 = fmaxf(a2, 0.f);

    // ---- q = q2 @ qw3 + qb3 : block reduction ----
    float part = a2 * qw3[t];
    #pragma unroll
    for (int o = 16; o > 0; o >>= 1)
        part += __shfl_down_sync(0xffffffffu, part, o);
    if ((t & 31) == 0) wsum[t >> 5] = part;
    __syncthreads();
    if (t == 0) {
        float s = qb3[0];
        #pragma unroll
        for (int i = 0; i < 8; i++) s += wsum[i];
        out[b] = s;
    }
}

extern "C" void kernel_launch(void* const* d_in, const int* in_sizes, int n_in,
                              void* d_out, int out_size)
{
    const float* obs       = (const float*)d_in[0];
    const float* obstacles = (const float*)d_in[1];
    const float* act       = (const float*)d_in[2];
    const float* ow1       = (const float*)d_in[3];
    const float* ob1       = (const float*)d_in[4];
    const float* ow2       = (const float*)d_in[5];
    const float* ob2       = (const float*)d_in[6];
    const float* qw1       = (const float*)d_in[7];
    const float* qb1       = (const float*)d_in[8];
    const float* qw2       = (const float*)d_in[9];
    const float* qb2       = (const float*)d_in[10];
    const float* qw3       = (const float*)d_in[11];
    const float* qb3       = (const float*)d_in[12];
    float* out             = (float*)d_out;

    setq_fused_kernel<<<BATCH, 256>>>(obs, obstacles, act,
                                      ow1, ob1, ow2, ob2,
                                      qw1, qb1, qw2, qb2, qw3, qb3,
                                      out);
}

// round 5
// speedup vs baseline: 1.0000x; 1.0000x over previous
#include <cuda_runtime.h>
#include <cuda_bf16.h>

// Problem constants
#define BATCH   4096
#define NOBST   128
#define VEH     18        // 2*6 + 6
#define OBD     4
#define F1      22        // VEH + OBD
#define H       256
#define OBSF    138
#define COMBF   396       // 138 + 256 + 2
#define TN      32        // obstacle tile
#define H1PAD   36        // padded row (multiple of 4 -> 16B aligned float4 rows)

__global__ __launch_bounds__(256)
void setq_fused_kernel(const float* __restrict__ obs,
                       const float* __restrict__ obstacles,
                       const float* __restrict__ act,
                       const float* __restrict__ ow1,
                       const float* __restrict__ ob1,
                       const float* __restrict__ ow2,
                       const float* __restrict__ ob2,
                       const float* __restrict__ qw1,
                       const float* __restrict__ qb1,
                       const float* __restrict__ qw2,
                       const float* __restrict__ qb2,
                       const float* __restrict__ qw3,
                       const float* __restrict__ qb3,
                       float* __restrict__ out)
{
    const int b = blockIdx.x;
    const int t = threadIdx.x;          // hidden channel 0..255

    __shared__ float obss[OBSF];        // full obs row (veh = obss[0..17])
    __shared__ float acts[2];
    __shared__ float masks[NOBST];
    __shared__ float obsts[OBD][TN];    // obstacle features for current tile
    __shared__ float h1s[H * H1PAD];    // h1 tile, layout [k][j], padded
    __shared__ float pooled[H];
    __shared__ float q1s[H];
    __shared__ float wsum[8];

    // ---- stage per-batch scalars ----
    if (t < OBSF)  obss[t]  = obs[b * OBSF + t];
    if (t < NOBST) masks[t] = obstacles[(b * 5 + 4) * NOBST + t];
    if (t < 2)     acts[t]  = act[b * 2 + t];
    __syncthreads();

    // ---- hoisted vehicle contribution to h1 channel t ----
    float base = ob1[t];
    #pragma unroll
    for (int f = 0; f < VEH; f++)
        base = fmaf(obss[f], ow1[f * H + t], base);
    const float w18 = ow1[(VEH + 0) * H + t];
    const float w19 = ow1[(VEH + 1) * H + t];
    const float w20 = ow1[(VEH + 2) * H + t];
    const float w21 = ow1[(VEH + 3) * H + t];
    const float ob2t = ob2[t];

    float pool = 0.f;

    // ---- obstacle MLP over 4 tiles of 32 ----
    for (int tile = 0; tile < NOBST / TN; tile++) {
        const int n0 = tile * TN;
        __syncthreads();   // previous tile's h1s reads done
        if (t < OBD * TN)
            obsts[t / TN][t % TN] =
                obstacles[(b * 5 + (t / TN)) * NOBST + n0 + (t % TN)];
        __syncthreads();

        // h1[t][j] for this tile: base + 4 obstacle-feature FMAs, relu
        #pragma unroll
        for (int j = 0; j < TN; j++) {
            float v = base;
            v = fmaf(w18, obsts[0][j], v);
            v = fmaf(w19, obsts[1][j], v);
            v = fmaf(w20, obsts[2][j], v);
            v = fmaf(w21, obsts[3][j], v);
            h1s[t * H1PAD + j] = fmaxf(v, 0.f);
        }
        __syncthreads();

        // h2 accumulation: acc[j] = sum_k h1[k][j] * ow2[k][t]
        float acc[TN];
        #pragma unroll
        for (int j = 0; j < TN; j++) acc[j] = 0.f;

        #pragma unroll 2
        for (int k = 0; k < H; k++) {
            const float w = ow2[k * H + t];               // coalesced, L1/L2 hit
            const float4* row = (const float4*)(h1s + k * H1PAD); // broadcast
            #pragma unroll
            for (int q = 0; q < 8; q++) {
                float4 a = row[q];
                acc[4 * q + 0] = fmaf(a.x, w, acc[4 * q + 0]);
                acc[4 * q + 1] = fmaf(a.y, w, acc[4 * q + 1]);
                acc[4 * q + 2] = fmaf(a.z, w, acc[4 * q + 2]);
                acc[4 * q + 3] = fmaf(a.w, w, acc[4 * q + 3]);
            }
        }

        // fused bias + relu + masked pooling (h2 never materialized)
        #pragma unroll
        for (int j = 0; j < TN; j++) {
            float h2 = fmaxf(acc[j] + ob2t, 0.f);
            pool = fmaf(masks[n0 + j], h2, pool);
        }
    }

    pooled[t] = pool;
    __syncthreads();

    // ---- Q head: q1 = relu(comb @ qw1 + qb1) ----
    float a1 = qb1[t];
    #pragma unroll 4
    for (int f = 0; f < OBSF; f++)
        a1 = fmaf(obss[f], qw1[f * H + t], a1);
    #pragma unroll 4
    for (int f = 0; f < H; f++)
        a1 = fmaf(pooled[f], qw1[(OBSF + f) * H + t], a1);
    a1 = fmaf(acts[0], qw1[(OBSF + H + 0) * H + t], a1);
    a1 = fmaf(acts[1], qw1[(OBSF + H + 1) * H + t], a1);
    q1s[t] = fmaxf(a1, 0.f);
    __syncthreads();

    // ---- q2 = relu(q1 @ qw2 + qb2) ----
    float a2 = qb2[t];
    #pragma unroll 4
    for (int k = 0; k < H; k++)
        a2 = fmaf(q1s[k], qw2[k * H + t], a2);
    a2 = fmaxf(a2, 0.f);

    // ---- q = q2 @ qw3 + qb3 : block reduction ----
    float part = a2 * qw3[t];
    #pragma unroll
    for (int o = 16; o > 0; o >>= 1)
        part += __shfl_down_sync(0xffffffffu, part, o);
    if ((t & 31) == 0) wsum[t >> 5] = part;
    __syncthreads();
    if (t == 0) {
        float s = qb3[0];
        #pragma unroll
        for (int i = 0; i < 8; i++) s += wsum[i];
        out[b] = s;
    }
}

extern "C" void kernel_launch(void* const* d_in, const int* in_sizes, int n_in,
                              void* d_out, int out_size)
{
    const float* obs       = (const float*)d_in[0];
    const float* obstacles = (const float*)d_in[1];
    const float* act       = (const float*)d_in[2];
    const float* ow1       = (const float*)d_in[3];
    const float* ob1       = (const float*)d_in[4];
    const float* ow2       = (const float*)d_in[5];
    const float* ob2       = (const float*)d_in[6];
    const float* qw1       = (const float*)d_in[7];
    const float* qb1       = (const float*)d_in[8];
    const float* qw2       = (const float*)d_in[9];
    const float* qb2       = (const float*)d_in[10];
    const float* qw3       = (const float*)d_in[11];
    const float* qb3       = (const float*)d_in[12];
    float* out             = (float*)d_out;

    setq_fused_kernel<<<BATCH, 256>>>(obs, obstacles, act,
                                      ow1, ob1, ow2, ob2,
                                      qw1, qb1, qw2, qb2, qw3, qb3,
                                      out);
}

// round 6
// speedup vs baseline: 1.0482x; 1.0482x over previous
#include <cuda_runtime.h>
#include <cuda_bf16.h>

// Problem constants
#define BATCH   4096
#define NOBST   128
#define VEH     18        // 2*6 + 6
#define OBD     4
#define H       256
#define OBSF    138
#define TN      16        // obstacle tile (8 tiles)
#define NTILE   (NOBST / TN)
#define TNP     20        // padded row: 20 floats = 80B (16B-aligned rows)

// ---- f32x2 packed helpers (sm_103a; ptxas never auto-generates FFMA2) ----
__device__ __forceinline__ unsigned long long pack2(float x, float y) {
    unsigned long long r;
    asm("mov.b64 %0, {%1, %2};" : "=l"(r) : "f"(x), "f"(y));
    return r;
}
__device__ __forceinline__ void unpack2(float &x, float &y, unsigned long long v) {
    asm("mov.b64 {%0, %1}, %2;" : "=f"(x), "=f"(y) : "l"(v));
}
__device__ __forceinline__ void fma2(unsigned long long &d,
                                     unsigned long long a,
                                     unsigned long long b) {
    asm("fma.rn.f32x2 %0, %1, %2, %0;" : "+l"(d) : "l"(a), "l"(b));
}

__global__ __launch_bounds__(256, 4)
void setq_fused_kernel(const float* __restrict__ obs,
                       const float* __restrict__ obstacles,
                       const float* __restrict__ act,
                       const float* __restrict__ ow1,
                       const float* __restrict__ ob1,
                       const float* __restrict__ ow2,
                       const float* __restrict__ ob2,
                       const float* __restrict__ qw1,
                       const float* __restrict__ qb1,
                       const float* __restrict__ qw2,
                       const float* __restrict__ qb2,
                       const float* __restrict__ qw3,
                       const float* __restrict__ qb3,
                       float* __restrict__ out)
{
    const int b = blockIdx.x;
    const int t = threadIdx.x;          // hidden channel 0..255

    __shared__ float obss[OBSF];
    __shared__ float acts[2];
    __shared__ float masks[NOBST];
    __shared__ float obsts[OBD][TN];
    __shared__ __align__(16) float h1s[H * TNP];   // ~20 KB
    __shared__ float pooled[H];
    __shared__ float q1s[H];
    __shared__ float wsum[8];

    // ---- stage per-batch scalars ----
    if (t < OBSF)  obss[t]  = obs[b * OBSF + t];
    if (t < NOBST) masks[t] = obstacles[(b * 5 + 4) * NOBST + t];
    if (t < 2)     acts[t]  = act[b * 2 + t];
    __syncthreads();

    // ---- hoisted vehicle contribution to h1 channel t ----
    float base = ob1[t];
    #pragma unroll
    for (int f = 0; f < VEH; f++)
        base = fmaf(obss[f], ow1[f * H + t], base);
    const float w18 = ow1[(VEH + 0) * H + t];
    const float w19 = ow1[(VEH + 1) * H + t];
    const float w20 = ow1[(VEH + 2) * H + t];
    const float w21 = ow1[(VEH + 3) * H + t];
    const float ob2t = ob2[t];

    float pool = 0.f;

    // ---- obstacle MLP over 8 tiles of 16 ----
    for (int tile = 0; tile < NTILE; tile++) {
        const int n0 = tile * TN;
        __syncthreads();   // previous tile's h1s/obsts reads done
        if (t < OBD * TN)
            obsts[t >> 4][t & 15] =
                obstacles[(b * 5 + (t >> 4)) * NOBST + n0 + (t & 15)];
        __syncthreads();

        // h1[t][j] for this tile: base + 4 obstacle-feature FMAs, relu
        #pragma unroll
        for (int j = 0; j < TN; j++) {
            float v = base;
            v = fmaf(w18, obsts[0][j], v);
            v = fmaf(w19, obsts[1][j], v);
            v = fmaf(w20, obsts[2][j], v);
            v = fmaf(w21, obsts[3][j], v);
            h1s[t * TNP + j] = fmaxf(v, 0.f);
        }
        __syncthreads();

        // h2 accumulation (packed): acc[j/2] += (h1[k][2j],h1[k][2j+1]) * (w,w)
        unsigned long long acc[8];
        #pragma unroll
        for (int i = 0; i < 8; i++) acc[i] = 0ULL;

        #pragma unroll 2
        for (int k = 0; k < H; k++) {
            const float w = ow2[k * H + t];                 // coalesced, L1/L2 hit
            const unsigned long long wp = pack2(w, w);
            const ulonglong2* row =
                (const ulonglong2*)(h1s + k * TNP);         // broadcast LDS.128
            ulonglong2 r0 = row[0];
            fma2(acc[0], r0.x, wp);
            fma2(acc[1], r0.y, wp);
            ulonglong2 r1 = row[1];
            fma2(acc[2], r1.x, wp);
            fma2(acc[3], r1.y, wp);
            ulonglong2 r2 = row[2];
            fma2(acc[4], r2.x, wp);
            fma2(acc[5], r2.y, wp);
            ulonglong2 r3 = row[3];
            fma2(acc[6], r3.x, wp);
            fma2(acc[7], r3.y, wp);
        }

        // fused bias + relu + masked pooling (h2 never materialized)
        #pragma unroll
        for (int i = 0; i < 8; i++) {
            float lo, hi;
            unpack2(lo, hi, acc[i]);
            float h2a = fmaxf(lo + ob2t, 0.f);
            float h2b = fmaxf(hi + ob2t, 0.f);
            pool = fmaf(masks[n0 + 2 * i + 0], h2a, pool);
            pool = fmaf(masks[n0 + 2 * i + 1], h2b, pool);
        }
    }

    pooled[t] = pool;
    __syncthreads();

    // ---- Q head: q1 = relu(comb @ qw1 + qb1) ----
    float a1 = qb1[t];
    #pragma unroll 4
    for (int f = 0; f < OBSF; f++)
        a1 = fmaf(obss[f], qw1[f * H + t], a1);
    #pragma unroll 4
    for (int f = 0; f < H; f++)
        a1 = fmaf(pooled[f], qw1[(OBSF + f) * H + t], a1);
    a1 = fmaf(acts[0], qw1[(OBSF + H + 0) * H + t], a1);
    a1 = fmaf(acts[1], qw1[(OBSF + H + 1) * H + t], a1);
    q1s[t] = fmaxf(a1, 0.f);
    __syncthreads();

    // ---- q2 = relu(q1 @ qw2 + qb2) ----
    float a2 = qb2[t];
    #pragma unroll 4
    for (int k = 0; k < H; k++)
        a2 = fmaf(q1s[k], qw2[k * H + t], a2);
    a2 = fmaxf(a2, 0.f);

    // ---- q = q2 @ qw3 + qb3 : block reduction ----
    float part = a2 * qw3[t];
    #pragma unroll
    for (int o = 16; o > 0; o >>= 1)
        part += __shfl_down_sync(0xffffffffu, part, o);
    if ((t & 31) == 0) wsum[t >> 5] = part;
    __syncthreads();
    if (t == 0) {
        float s = qb3[0];
        #pragma unroll
        for (int i = 0; i < 8; i++) s += wsum[i];
        out[b] = s;
    }
}

extern "C" void kernel_launch(void* const* d_in, const int* in_sizes, int n_in,
                              void* d_out, int out_size)
{
    const float* obs       = (const float*)d_in[0];
    const float* obstacles = (const float*)d_in[1];
    const float* act       = (const float*)d_in[2];
    const float* ow1       = (const float*)d_in[3];
    const float* ob1       = (const float*)d_in[4];
    const float* ow2       = (const float*)d_in[5];
    const float* ob2       = (const float*)d_in[6];
    const float* qw1       = (const float*)d_in[7];
    const float* qb1       = (const float*)d_in[8];
    const float* qw2       = (const float*)d_in[9];
    const float* qb2       = (const float*)d_in[10];
    const float* qw3       = (const float*)d_in[11];
    const float* qb3       = (const float*)d_in[12];
    float* out             = (float*)d_out;

    setq_fused_kernel<<<BATCH, 256>>>(obs, obstacles, act,
                                      ow1, ob1, ow2, ob2,
                                      qw1, qb1, qw2, qb2, qw3, qb3,
                                      out);
}

// round 7
// speedup vs baseline: 1.0994x; 1.0489x over previous
#include <cuda_runtime.h>
#include <cuda_bf16.h>

// Problem constants
#define BATCH   4096
#define NOBST   128
#define VEH     18        // 2*6 + 6
#define OBD     4
#define H       256
#define OBSF    138
#define TN      32        // obstacle tile (4 tiles)
#define NTILE   (NOBST / TN)
#define H1PAD   36        // 144B rows: 16B-aligned, rotating bank pattern
#define TM      8         // channels per thread (GEMM)
#define TNR     4         // obstacles per thread (GEMM)

typedef unsigned long long ull;

// ---- f32x2 packed helpers (sm_103a; ptxas never auto-generates FFMA2) ----
__device__ __forceinline__ ull pack2(float x, float y) {
    ull r;
    asm("mov.b64 %0, {%1, %2};" : "=l"(r) : "f"(x), "f"(y));
    return r;
}
__device__ __forceinline__ void unpack2(float &x, float &y, ull v) {
    asm("mov.b64 {%0, %1}, %2;" : "=f"(x), "=f"(y) : "l"(v));
}
__device__ __forceinline__ void fma2(ull &d, ull a, ull b) {
    asm("fma.rn.f32x2 %0, %1, %2, %0;" : "+l"(d) : "l"(a), "l"(b));
}

__global__ __launch_bounds__(256, 2)
void setq_fused_kernel(const float* __restrict__ obs,
                       const float* __restrict__ obstacles,
                       const float* __restrict__ act,
                       const float* __restrict__ ow1,
                       const float* __restrict__ ob1,
                       const float* __restrict__ ow2,
                       const float* __restrict__ ob2,
                       const float* __restrict__ qw1,
                       const float* __restrict__ qb1,
                       const float* __restrict__ qw2,
                       const float* __restrict__ qb2,
                       const float* __restrict__ qw3,
                       const float* __restrict__ qb3,
                       float* __restrict__ out)
{
    const int b  = blockIdx.x;
    const int t  = threadIdx.x;       // 0..255
    const int jb = t & 7;             // obstacle block 0..7 (4 obstacles each)
    const int tb = t >> 3;            // channel block 0..31 (8 channels each)
    const int c0 = tb * TM;           // base output channel for GEMM

    __shared__ float obss[OBSF];
    __shared__ float acts[2];
    __shared__ float masks[NOBST];
    __shared__ float obsts[OBD][TN];
    __shared__ __align__(16) float h1s[H * H1PAD];   // 36 KB
    __shared__ float pooled[H];
    __shared__ float q1s[H];
    __shared__ float wsum[8];

    // ---- stage per-batch scalars ----
    if (t < OBSF)  obss[t]  = obs[b * OBSF + t];
    if (t < NOBST) masks[t] = obstacles[(b * 5 + 4) * NOBST + t];
    if (t < 2)     acts[t]  = act[b * 2 + t];
    __syncthreads();

    // ---- hoisted vehicle contribution to h1 channel t (h1 production role) ----
    float base = ob1[t];
    #pragma unroll
    for (int f = 0; f < VEH; f++)
        base = fmaf(obss[f], ow1[f * H + t], base);
    const float w18 = ow1[(VEH + 0) * H + t];
    const float w19 = ow1[(VEH + 1) * H + t];
    const float w20 = ow1[(VEH + 2) * H + t];
    const float w21 = ow1[(VEH + 3) * H + t];

    // ---- per-thread GEMM-output params: ob2 for channels [c0, c0+8) ----
    float ob2v[TM];
    {
        float4 a = *(const float4*)(ob2 + c0);
        float4 bq = *(const float4*)(ob2 + c0 + 4);
        ob2v[0] = a.x;  ob2v[1] = a.y;  ob2v[2] = a.z;  ob2v[3] = a.w;
        ob2v[4] = bq.x; ob2v[5] = bq.y; ob2v[6] = bq.z; ob2v[7] = bq.w;
    }

    float pool[TM];
    #pragma unroll
    for (int c = 0; c < TM; c++) pool[c] = 0.f;

    // ---- obstacle MLP over 4 tiles of 32 ----
    for (int tile = 0; tile < NTILE; tile++) {
        const int n0 = tile * TN;
        __syncthreads();   // previous tile's h1s/obsts reads complete
        if (t < OBD * TN)
            obsts[t >> 5][t & 31] =
                obstacles[(b * 5 + (t >> 5)) * NOBST + n0 + (t & 31)];
        __syncthreads();

        // phase A: h1[t][j] for j in [0,32): base + 4 obstacle FMAs, relu
        #pragma unroll
        for (int jq = 0; jq < TN / 4; jq++) {
            float4 v4;
            float* vp = (float*)&v4;
            #pragma unroll
            for (int u = 0; u < 4; u++) {
                const int j = jq * 4 + u;
                float v = base;
                v = fmaf(w18, obsts[0][j], v);
                v = fmaf(w19, obsts[1][j], v);
                v = fmaf(w20, obsts[2][j], v);
                v = fmaf(w21, obsts[3][j], v);
                vp[u] = fmaxf(v, 0.f);
            }
            *(float4*)(h1s + t * H1PAD + jq * 4) = v4;
        }
        __syncthreads();

        // GEMM: acc[cp][j] (channels paired in f32x2 lanes) over k
        ull acc[16];
        #pragma unroll
        for (int i = 0; i < 16; i++) acc[i] = 0ULL;

        const float* Ap = h1s + jb * TNR;
        const float* Wp = ow2 + c0;

        #pragma unroll 2
        for (int k = 0; k < H; k++) {
            // weight pairs: (w[c0],w[c0+1]) etc. — already f32x2-packed in memory
            ulonglong2 w01 = *(const ulonglong2*)(Wp + k * H);
            ulonglong2 w45 = *(const ulonglong2*)(Wp + k * H + 4);
            // A: 4 obstacles, duplicated into both f32x2 lanes
            float4 a = *(const float4*)(Ap + k * H1PAD);
            ull a0 = pack2(a.x, a.x);
            ull a1 = pack2(a.y, a.y);
            ull a2 = pack2(a.z, a.z);
            ull a3 = pack2(a.w, a.w);

            fma2(acc[0],  a0, w01.x); fma2(acc[1],  a1, w01.x);
            fma2(acc[2],  a2, w01.x); fma2(acc[3],  a3, w01.x);
            fma2(acc[4],  a0, w01.y); fma2(acc[5],  a1, w01.y);
            fma2(acc[6],  a2, w01.y); fma2(acc[7],  a3, w01.y);
            fma2(acc[8],  a0, w45.x); fma2(acc[9],  a1, w45.x);
            fma2(acc[10], a2, w45.x); fma2(acc[11], a3, w45.x);
            fma2(acc[12], a0, w45.y); fma2(acc[13], a1, w45.y);
            fma2(acc[14], a2, w45.y); fma2(acc[15], a3, w45.y);
        }

        // fused bias + relu + masked pooling into register pool
        float m[TNR];
        #pragma unroll
        for (int j = 0; j < TNR; j++)
            m[j] = masks[n0 + jb * TNR + j];

        #pragma unroll
        for (int cp = 0; cp < 4; cp++) {
            #pragma unroll
            for (int j = 0; j < TNR; j++) {
                float lo, hi;
                unpack2(lo, hi, acc[cp * 4 + j]);
                float h2a = fmaxf(lo + ob2v[2 * cp + 0], 0.f);
                float h2b = fmaxf(hi + ob2v[2 * cp + 1], 0.f);
                pool[2 * cp + 0] = fmaf(m[j], h2a, pool[2 * cp + 0]);
                pool[2 * cp + 1] = fmaf(m[j], h2b, pool[2 * cp + 1]);
            }
        }
    }

    // ---- reduce pool across the 8 jb lanes (consecutive lanes, same warp) ----
    #pragma unroll
    for (int o = 4; o > 0; o >>= 1) {
        #pragma unroll
        for (int c = 0; c < TM; c++)
            pool[c] += __shfl_down_sync(0xffffffffu, pool[c], o, 8);
    }
    if (jb == 0) {
        #pragma unroll
        for (int c = 0; c < TM; c++)
            pooled[c0 + c] = pool[c];
    }
    __syncthreads();

    // ---- Q head: q1 = relu(comb @ qw1 + qb1) ----
    float a1 = qb1[t];
    #pragma unroll 4
    for (int f = 0; f < OBSF; f++)
        a1 = fmaf(obss[f], qw1[f * H + t], a1);
    #pragma unroll 4
    for (int f = 0; f < H; f++)
        a1 = fmaf(pooled[f], qw1[(OBSF + f) * H + t], a1);
    a1 = fmaf(acts[0], qw1[(OBSF + H + 0) * H + t], a1);
    a1 = fmaf(acts[1], qw1[(OBSF + H + 1) * H + t], a1);
    q1s[t] = fmaxf(a1, 0.f);
    __syncthreads();

    // ---- q2 = relu(q1 @ qw2 + qb2) ----
    float a2 = qb2[t];
    #pragma unroll 4
    for (int k = 0; k < H; k++)
        a2 = fmaf(q1s[k], qw2[k * H + t], a2);
    a2 = fmaxf(a2, 0.f);

    // ---- q = q2 @ qw3 + qb3 : block reduction ----
    float part = a2 * qw3[t];
    #pragma unroll
    for (int o = 16; o > 0; o >>= 1)
        part += __shfl_down_sync(0xffffffffu, part, o);
    if ((t & 31) == 0) wsum[t >> 5] = part;
    __syncthreads();
    if (t == 0) {
        float s = qb3[0];
        #pragma unroll
        for (int i = 0; i < 8; i++) s += wsum[i];
        out[b] = s;
    }
}

extern "C" void kernel_launch(void* const* d_in, const int* in_sizes, int n_in,
                              void* d_out, int out_size)
{
    const float* obs       = (const float*)d_in[0];
    const float* obstacles = (const float*)d_in[1];
    const float* act       = (const float*)d_in[2];
    const float* ow1       = (const float*)d_in[3];
    const float* ob1       = (const float*)d_in[4];
    const float* ow2       = (const float*)d_in[5];
    const float* ob2       = (const float*)d_in[6];
    const float* qw1       = (const float*)d_in[7];
    const float* qb1       = (const float*)d_in[8];
    const float* qw2       = (const float*)d_in[9];
    const float* qb2       = (const float*)d_in[10];
    const float* qw3       = (const float*)d_in[11];
    const float* qb3       = (const float*)d_in[12];
    float* out             = (float*)d_out;

    setq_fused_kernel<<<BATCH, 256>>>(obs, obstacles, act,
                                      ow1, ob1, ow2, ob2,
                                      qw1, qb1, qw2, qb2, qw3, qb3,
                                      out);
}

// round 9
// speedup vs baseline: 2.0467x; 1.8617x over previous
#include <cuda_runtime.h>
#include <cstdint>

// ---------------- problem constants ----------------
#define BATCH 4096
#define NOBST 128
#define VEH   18
#define OBD   4
#define H     256
#define OBSF  138
#define KC    32                // K per chunk
#define NCHUNK 8                // 256/32
#define LDA   36                // padded row (floats) for A/B smem

__device__ float g_ow2T[H * H]; // ow2 transposed [n][k], tf32-rounded

// ---------------- smem layout ----------------
struct SMem {
    uint32_t A[NOBST * LDA];    // h1 chunk [m][kc], tf32 bits     18432 B
    uint32_t Bs[H * LDA];       // ow2T chunk [n][kc], tf32 bits   36864 B
    float  obss[144];
    float  acts[4];
    float  masks[128];
    float4 obst4[128];          // [m] -> 4 obstacle features
    float  base[256];
    float4 w4[256];             // ow1 rows 18..21 per channel
    float  ob2s[256];
    float  pooled[256];
    float  comb[400];
    float  qpart[512];
    float  q1s[256];
    float  wsum[8];
};
#define SMEM_BYTES (sizeof(SMem))

// ---------------- helpers ----------------
__device__ __forceinline__ uint32_t f2tf32(float v) {
    uint32_t u;
    asm("cvt.rna.tf32.f32 %0, %1;" : "=r"(u) : "f"(v));
    return u;
}
__device__ __forceinline__ void mma_tf32(float* c,
                                         uint32_t a0, uint32_t a1, uint32_t a2, uint32_t a3,
                                         uint32_t b0, uint32_t b1) {
    asm volatile(
        "mma.sync.aligned.m16n8k8.row.col.f32.tf32.tf32.f32 "
        "{%0,%1,%2,%3}, {%4,%5,%6,%7}, {%8,%9}, {%0,%1,%2,%3};"
        : "+f"(c[0]), "+f"(c[1]), "+f"(c[2]), "+f"(c[3])
        : "r"(a0), "r"(a1), "r"(a2), "r"(a3), "r"(b0), "r"(b1));
}

// ---------------- prep: transpose + tf32-round ow2 ----------------
__global__ void transpose_ow2(const float* __restrict__ ow2) {
    __shared__ float tile[32][33];
    const int tx = threadIdx.x, ty = threadIdx.y;
    const int kt = blockIdx.y * 32, nt = blockIdx.x * 32;
    #pragma unroll
    for (int i = 0; i < 4; i++)
        tile[ty + 8 * i][tx] = ow2[(kt + ty + 8 * i) * H + nt + tx];
    __syncthreads();
    #pragma unroll
    for (int i = 0; i < 4; i++)
        g_ow2T[(nt + ty + 8 * i) * H + kt + tx] =
            __uint_as_float(f2tf32(tile[tx][ty + 8 * i]));
}

// ---------------- main fused kernel: 1 CTA (512 thr) per batch row ----------------
__global__ __launch_bounds__(512, 1)
void setq_tc_kernel(const float* __restrict__ obs,
                    const float* __restrict__ obstacles,
                    const float* __restrict__ act,
                    const float* __restrict__ ow1,
                    const float* __restrict__ ob1,
                    const float* __restrict__ ob2,
                    const float* __restrict__ qw1,
                    const float* __restrict__ qb1,
                    const float* __restrict__ qw2,
                    const float* __restrict__ qb2,
                    const float* __restrict__ qw3,
                    const float* __restrict__ qb3,
                    float* __restrict__ out)
{
    extern __shared__ char smraw[];
    SMem* S = (SMem*)smraw;
    const int b    = blockIdx.x;
    const int t    = threadIdx.x;
    const int w    = t >> 5;
    const int lane = t & 31;

    // ---- stage per-batch data ----
    if (t < OBSF)  S->obss[t]  = obs[b * OBSF + t];
    if (t < 128)   S->masks[t] = obstacles[(b * 5 + 4) * NOBST + t];
    if (t < 2)     S->acts[t]  = act[b * 2 + t];
    if (t >= 256) {
        int c = t - 256;
        S->ob2s[c]   = ob2[c];
        S->pooled[c] = 0.f;
    }
    {   // obst4[m] = obstacles[b, 0..3, m]
        int j = t >> 7, m = t & 127;
        ((float*)&S->obst4[m])[j] = obstacles[(b * 5 + j) * NOBST + m];
    }
    __syncthreads();

    // ---- per-channel hoisted base + last-4 weights ----
    if (t < 256) {
        float bb = ob1[t];
        #pragma unroll
        for (int f = 0; f < VEH; f++)
            bb = fmaf(S->obss[f], ow1[f * H + t], bb);
        S->base[t] = bb;
        S->w4[t] = make_float4(ow1[(VEH + 0) * H + t], ow1[(VEH + 1) * H + t],
                               ow1[(VEH + 2) * H + t], ow1[(VEH + 3) * H + t]);
    }

    // ---- GEMM: D[m=128 obst][n=256 chan] = h1 @ ow2, K chunked by 32 ----
    const int m0 = (w & 7) * 16;      // warp m-band
    const int nb = (w >> 3) * 128;    // warp n-half
    const int r  = lane >> 2;         // fragment row group
    const int q  = lane & 3;          // fragment k/col group

    float acc[64];
    #pragma unroll
    for (int i = 0; i < 64; i++) acc[i] = 0.f;

    const int cl = t & 31;            // channel-in-chunk for production
    const int mg = t >> 5;            // m-group (8 rows each)

    for (int kc = 0; kc < NCHUNK; kc++) {
        __syncthreads();              // prev MMA done reading A/Bs (and base ready)

        // produce A chunk: h1[m][kc*32 + cl]
        {
            const int c = kc * 32 + cl;
            const float bb = S->base[c];
            const float4 wv = S->w4[c];
            #pragma unroll
            for (int mi = 0; mi < 8; mi++) {
                const int m = mg * 8 + mi;
                float4 o = S->obst4[m];           // warp-broadcast
                float v = bb;
                v = fmaf(wv.x, o.x, v);
                v = fmaf(wv.y, o.y, v);
                v = fmaf(wv.z, o.z, v);
                v = fmaf(wv.w, o.w, v);
                S->A[m * LDA + cl] = f2tf32(fmaxf(v, 0.f));
            }
        }
        // stage B chunk: ow2T[n][kc*32 .. +31] (already tf32-rounded)
        {
            const int n  = t >> 1;
            const int kq = (t & 1) * 16;
            const float4* src = (const float4*)(g_ow2T + n * H + kc * KC + kq);
            float4* dst = (float4*)((float*)S->Bs + n * LDA + kq);
            #pragma unroll
            for (int i = 0; i < 4; i++) dst[i] = src[i];
        }
        __syncthreads();

        // MMA accumulate over this chunk (4 k-steps of 8)
        #pragma unroll
        for (int s = 0; s < 4; s++) {
            const int ka = 8 * s + q;
            uint32_t a0 = S->A[(m0 + r)     * LDA + ka];
            uint32_t a1 = S->A[(m0 + r + 8) * LDA + ka];
            uint32_t a2 = S->A[(m0 + r)     * LDA + ka + 4];
            uint32_t a3 = S->A[(m0 + r + 8) * LDA + ka + 4];
            #pragma unroll
            for (int tile = 0; tile < 16; tile++) {
                uint32_t b0 = S->Bs[(nb + tile * 8 + r) * LDA + ka];
                uint32_t b1 = S->Bs[(nb + tile * 8 + r) * LDA + ka + 4];
                mma_tf32(acc + tile * 4, a0, a1, a2, a3, b0, b1);
            }
        }
    }

    // ---- epilogue: bias + relu + masked pool, in registers ----
    {
        const float mk0 = S->masks[m0 + r];
        const float mk1 = S->masks[m0 + r + 8];
        #pragma unroll
        for (int tile = 0; tile < 16; tile++) {
            const int n = nb + tile * 8 + 2 * q;
            const float o0 = S->ob2s[n], o1 = S->ob2s[n + 1];
            float v0 = mk0 * fmaxf(acc[tile * 4 + 0] + o0, 0.f)
                     + mk1 * fmaxf(acc[tile * 4 + 2] + o0, 0.f);
            float v1 = mk0 * fmaxf(acc[tile * 4 + 1] + o1, 0.f)
                     + mk1 * fmaxf(acc[tile * 4 + 3] + o1, 0.f);
            #pragma unroll
            for (int o = 4; o <= 16; o <<= 1) {
                v0 += __shfl_xor_sync(0xffffffffu, v0, o);
                v1 += __shfl_xor_sync(0xffffffffu, v1, o);
            }
            if (lane < 4) {
                atomicAdd(&S->pooled[nb + tile * 8 + 2 * lane],     v0);
                atomicAdd(&S->pooled[nb + tile * 8 + 2 * lane + 1], v1);
            }
        }
    }
    __syncthreads();

    // ---- build comb = [obs | pooled | act] ----
    if (t < OBSF)               S->comb[t] = S->obss[t];
    if (t >= 256 && t < 512)    S->comb[OBSF + (t - 256)] = S->pooled[t - 256];
    if (t >= 138 && t < 140)    S->comb[OBSF + H + (t - 138)] = S->acts[t - 138];
    __syncthreads();

    // ---- Q head (exact fp32, k-split across 512 threads) ----
    const int half = t >> 8;
    const int c    = t & 255;
    {
        const int k0 = half ? 198 : 0;
        const int k1 = half ? 396 : 198;
        float a1 = half ? 0.f : qb1[c];
        #pragma unroll 4
        for (int k = k0; k < k1; k++)
            a1 = fmaf(S->comb[k], qw1[k * H + c], a1);
        S->qpart[half * 256 + c] = a1;
    }
    __syncthreads();
    if (t < 256) S->q1s[t] = fmaxf(S->qpart[t] + S->qpart[256 + t], 0.f);
    __syncthreads();
    {
        const int k0 = half * 128;
        float a2 = half ? 0.f : qb2[c];
        #pragma unroll 4
        for (int k = k0; k < k0 + 128; k++)
            a2 = fmaf(S->q1s[k], qw2[k * H + c], a2);
        S->qpart[half * 256 + c] = a2;
    }
    __syncthreads();
    if (t < 256) {
        float q2 = fmaxf(S->qpart[t] + S->qpart[256 + t], 0.f);
        float part = q2 * qw3[t];
        #pragma unroll
        for (int o = 16; o > 0; o >>= 1)
            part += __shfl_down_sync(0xffffffffu, part, o);
        if (lane == 0) S->wsum[w] = part;
    }
    __syncthreads();
    if (t == 0) {
        float s = qb3[0];
        #pragma unroll
        for (int i = 0; i < 8; i++) s += S->wsum[i];
        out[b] = s;
    }
}

extern "C" void kernel_launch(void* const* d_in, const int* in_sizes, int n_in,
                              void* d_out, int out_size)
{
    const float* obs       = (const float*)d_in[0];
    const float* obstacles = (const float*)d_in[1];
    const float* act       = (const float*)d_in[2];
    const float* ow1       = (const float*)d_in[3];
    const float* ob1       = (const float*)d_in[4];
    const float* ow2       = (const float*)d_in[5];
    const float* ob2       = (const float*)d_in[6];
    const float* qw1       = (const float*)d_in[7];
    const float* qb1       = (const float*)d_in[8];
    const float* qw2       = (const float*)d_in[9];
    const float* qb2       = (const float*)d_in[10];
    const float* qw3       = (const float*)d_in[11];
    const float* qb3       = (const float*)d_in[12];
    float* out             = (float*)d_out;

    static_assert(sizeof(SMem) < 100 * 1024, "smem");
    cudaFuncSetAttribute(setq_tc_kernel,
                         cudaFuncAttributeMaxDynamicSharedMemorySize, SMEM_BYTES);

    transpose_ow2<<<dim3(8, 8), dim3(32, 8)>>>(ow2);
    setq_tc_kernel<<<BATCH, 512, SMEM_BYTES>>>(obs, obstacles, act,
                                               ow1, ob1, ob2,
                                               qw1, qb1, qw2, qb2, qw3, qb3,
                                               out);
}

// round 10
// speedup vs baseline: 5.1815x; 2.5316x over previous
#include <cuda_runtime.h>
#include <cuda_fp16.h>
#include <cstdint>

// ---------------- problem constants ----------------
#define BATCH 4096
#define NOBST 128
#define VEH   18
#define H     256
#define OBSF  138
#define KC    32
#define NCHUNK 8
#define LDAH  40     // halves per A smem row (80B: bank-conflict-free)
#define LDBH  40     // halves per B smem row

__device__ __half g_ow2T[H * H];        // ow2 transposed [n][k], half
__device__ float  g_pooled[BATCH * H];  // encoder -> Q-head scratch

// ---------------- encoder smem ----------------
struct EncSmem {
    __half Ah[2][NOBST * LDAH];   // h1 chunk double-buffer   20480 B
    __half Bh[2][H * LDBH];       // ow2T chunk double-buffer 40960 B
    float4 obst4[NOBST];
    float  masks[NOBST];
    float  base[H];
    float4 w4[H];
    float  ob2s[H];
    float  pooled_s[H];
    float  veh[24];
};

// ---------------- Q-head smem ----------------
#define R2  32      // batch rows per CTA
#define CLD 36      // padded row (floats)
struct QSmem {
    float combT[396 * CLD];   // [k][r]   57024 B
    float q1T[H * CLD];       // [k][r]   36864 B
    float wpart[8 * R2];
};

// ---------------- helpers ----------------
__device__ __forceinline__ void mma16816(float* c,
    uint32_t a0, uint32_t a1, uint32_t a2, uint32_t a3,
    uint32_t b0, uint32_t b1)
{
    asm volatile(
        "mma.sync.aligned.m16n8k16.row.col.f32.f16.f16.f32 "
        "{%0,%1,%2,%3}, {%4,%5,%6,%7}, {%8,%9}, {%0,%1,%2,%3};"
        : "+f"(c[0]), "+f"(c[1]), "+f"(c[2]), "+f"(c[3])
        : "r"(a0), "r"(a1), "r"(a2), "r"(a3), "r"(b0), "r"(b1));
}

// ---------------- prep: transpose ow2 -> half [n][k] ----------------
__global__ void prep_ow2(const float* __restrict__ ow2) {
    __shared__ float tile[32][33];
    const int tx = threadIdx.x, ty = threadIdx.y;
    const int kt = blockIdx.y * 32, nt = blockIdx.x * 32;
    #pragma unroll
    for (int i = 0; i < 4; i++)
        tile[ty + 8 * i][tx] = ow2[(kt + ty + 8 * i) * H + nt + tx];
    __syncthreads();
    #pragma unroll
    for (int i = 0; i < 4; i++)
        g_ow2T[(nt + ty + 8 * i) * H + kt + tx] = __float2half(tile[tx][ty + 8 * i]);
}

// ---------------- encoder: 1 CTA (512 thr) per batch row ----------------
__device__ __forceinline__ void produce_chunk(EncSmem* S, int chunk, int buf, int t) {
    const int cl = t & 31;            // k within chunk
    const int mg = t >> 5;            // m-group (8 rows)
    const int c  = chunk * 32 + cl;
    const float bb  = S->base[c];
    const float4 wv = S->w4[c];
    __half* dst = S->Ah[buf];
    #pragma unroll
    for (int mi = 0; mi < 8; mi++) {
        const int m = mg * 8 + mi;
        float4 o = S->obst4[m];
        float v = bb;
        v = fmaf(wv.x, o.x, v);
        v = fmaf(wv.y, o.y, v);
        v = fmaf(wv.z, o.z, v);
        v = fmaf(wv.w, o.w, v);
        dst[m * LDAH + cl] = __float2half(fmaxf(v, 0.f));
    }
}

__global__ __launch_bounds__(512, 1)
void setq_enc(const float* __restrict__ obs,
              const float* __restrict__ obstacles,
              const float* __restrict__ ow1,
              const float* __restrict__ ob1,
              const float* __restrict__ ob2)
{
    extern __shared__ char smraw[];
    EncSmem* S = (EncSmem*)smraw;
    const int b = blockIdx.x;
    const int t = threadIdx.x;
    const int w = t >> 5, lane = t & 31;

    // ---- stage per-batch data ----
    if (t < VEH) S->veh[t] = obs[b * OBSF + t];
    if (t >= 128 && t < 256) S->masks[t - 128] = obstacles[(b * 5 + 4) * NOBST + (t - 128)];
    if (t >= 256) { int c = t - 256; S->ob2s[c] = ob2[c]; S->pooled_s[c] = 0.f; }
    { int j = t >> 7, m = t & 127;
      ((float*)&S->obst4[m])[j] = obstacles[(b * 5 + j) * NOBST + m]; }
    __syncthreads();

    // ---- hoisted vehicle part per channel ----
    if (t < H) {
        float bb = ob1[t];
        #pragma unroll
        for (int f = 0; f < VEH; f++)
            bb = fmaf(S->veh[f], ow1[f * H + t], bb);
        S->base[t] = bb;
        S->w4[t] = make_float4(ow1[18 * H + t], ow1[19 * H + t],
                               ow1[20 * H + t], ow1[21 * H + t]);
    }
    __syncthreads();

    // ---- chunk 0: produce A, stage B ----
    produce_chunk(S, 0, 0, t);
    {
        const int n = t >> 1, part = t & 1;
        const __half* src = g_ow2T + n * H + 0 * KC + part * 16;
        uint4 v0 = ((const uint4*)src)[0];
        uint4 v1 = ((const uint4*)src)[1];
        __half* dst = S->Bh[0] + n * LDBH + part * 16;
        ((uint4*)dst)[0] = v0;
        ((uint4*)dst)[1] = v1;
    }
    __syncthreads();

    // ---- GEMM: D[m=128][n=256] = h1 @ ow2, warp tile m32 x n64 ----
    const int m0 = (w & 3) * 32;
    const int nq = (w >> 2) * 64;
    const int r  = lane >> 2;
    const int q  = lane & 3;

    float acc[64];
    #pragma unroll
    for (int i = 0; i < 64; i++) acc[i] = 0.f;

    for (int kc = 0; kc < NCHUNK; kc++) {
        const int bi = kc & 1;
        uint4 p0, p1;
        if (kc < NCHUNK - 1) {   // prefetch next B chunk (global, overlaps MMA)
            const __half* src = g_ow2T + (t >> 1) * H + (kc + 1) * KC + (t & 1) * 16;
            p0 = ((const uint4*)src)[0];
            p1 = ((const uint4*)src)[1];
        }
        const __half* Ab = S->Ah[bi];
        const __half* Bb = S->Bh[bi];
        #pragma unroll
        for (int s = 0; s < 2; s++) {
            const int kb = 16 * s + 2 * q;
            uint32_t a0 = *(const uint32_t*)(Ab + (m0 + r)      * LDAH + kb);
            uint32_t a1 = *(const uint32_t*)(Ab + (m0 + r + 8)  * LDAH + kb);
            uint32_t a2 = *(const uint32_t*)(Ab + (m0 + r)      * LDAH + kb + 8);
            uint32_t a3 = *(const uint32_t*)(Ab + (m0 + r + 8)  * LDAH + kb + 8);
            uint32_t a4 = *(const uint32_t*)(Ab + (m0 + 16 + r) * LDAH + kb);
            uint32_t a5 = *(const uint32_t*)(Ab + (m0 + 24 + r) * LDAH + kb);
            uint32_t a6 = *(const uint32_t*)(Ab + (m0 + 16 + r) * LDAH + kb + 8);
            uint32_t a7 = *(const uint32_t*)(Ab + (m0 + 24 + r) * LDAH + kb + 8);
            #pragma unroll
            for (int j = 0; j < 8; j++) {
                const __half* bp = Bb + (nq + 8 * j + r) * LDBH + kb;
                uint32_t b0 = *(const uint32_t*)bp;
                uint32_t b1 = *(const uint32_t*)(bp + 8);
                mma16816(acc + j * 4,      a0, a1, a2, a3, b0, b1);
                mma16816(acc + 32 + j * 4, a4, a5, a6, a7, b0, b1);
            }
        }
        if (kc < NCHUNK - 1) {
            const int nb = bi ^ 1;
            produce_chunk(S, kc + 1, nb, t);
            __half* dst = S->Bh[nb] + (t >> 1) * LDBH + (t & 1) * 16;
            ((uint4*)dst)[0] = p0;
            ((uint4*)dst)[1] = p1;
        }
        __syncthreads();
    }

    // ---- epilogue: bias + relu + masked pool ----
    {
        const float mk0 = S->masks[m0 + r];
        const float mk1 = S->masks[m0 + r + 8];
        const float mk2 = S->masks[m0 + 16 + r];
        const float mk3 = S->masks[m0 + 24 + r];
        #pragma unroll
        for (int j = 0; j < 8; j++) {
            const int n = nq + 8 * j + 2 * q;
            const float o0 = S->ob2s[n], o1 = S->ob2s[n + 1];
            const float* c0 = acc + j * 4;
            const float* c1 = acc + 32 + j * 4;
            float v0 = mk0 * fmaxf(c0[0] + o0, 0.f) + mk1 * fmaxf(c0[2] + o0, 0.f)
                     + mk2 * fmaxf(c1[0] + o0, 0.f) + mk3 * fmaxf(c1[2] + o0, 0.f);
            float v1 = mk0 * fmaxf(c0[1] + o1, 0.f) + mk1 * fmaxf(c0[3] + o1, 0.f)
                     + mk2 * fmaxf(c1[1] + o1, 0.f) + mk3 * fmaxf(c1[3] + o1, 0.f);
            #pragma unroll
            for (int o = 4; o <= 16; o <<= 1) {
                v0 += __shfl_xor_sync(0xffffffffu, v0, o);
                v1 += __shfl_xor_sync(0xffffffffu, v1, o);
            }
            if (lane < 4) {
                atomicAdd(&S->pooled_s[nq + 8 * j + 2 * lane],     v0);
                atomicAdd(&S->pooled_s[nq + 8 * j + 2 * lane + 1], v1);
            }
        }
    }
    __syncthreads();
    if (t < H) g_pooled[b * H + t] = S->pooled_s[t];
}

// ---------------- Q-head: batched, exact fp32 ----------------
__global__ __launch_bounds__(256, 2)
void setq_qhead(const float* __restrict__ obs,
                const float* __restrict__ act,
                const float* __restrict__ qw1,
                const float* __restrict__ qb1,
                const float* __restrict__ qw2,
                const float* __restrict__ qb2,
                const float* __restrict__ qw3,
                const float* __restrict__ qb3,
                float* __restrict__ out)
{
    extern __shared__ char smraw[];
    QSmem* S = (QSmem*)smraw;
    const int rb = blockIdx.x * R2;
    const int t  = threadIdx.x;
    const int w  = t >> 5, lane = t & 31;

    // ---- load comb transposed: [k][r] ----
    {
        const int r = t >> 3, f0 = t & 7;
        for (int f = f0; f < OBSF; f += 8)
            S->combT[f * CLD + r] = obs[(rb + r) * OBSF + f];
        for (int c = f0; c < H; c += 8)
            S->combT[(OBSF + c) * CLD + r] = g_pooled[(rb + r) * H + c];
        if (f0 < 2)
            S->combT[(OBSF + H + f0) * CLD + r] = act[(rb + r) * 2 + f0];
    }
    __syncthreads();

    const int c = t;      // channel
    // ---- q1 = relu(comb @ qw1 + qb1), 32 rows per thread ----
    float acc1[R2];
    #pragma unroll
    for (int i = 0; i < R2; i++) acc1[i] = 0.f;
    #pragma unroll 4
    for (int k = 0; k < 396; k++) {
        const float wv = qw1[k * H + c];
        const float4* row = (const float4*)(S->combT + k * CLD);
        #pragma unroll
        for (int u = 0; u < 8; u++) {
            float4 a = row[u];
            acc1[4 * u + 0] = fmaf(a.x, wv, acc1[4 * u + 0]);
            acc1[4 * u + 1] = fmaf(a.y, wv, acc1[4 * u + 1]);
            acc1[4 * u + 2] = fmaf(a.z, wv, acc1[4 * u + 2]);
            acc1[4 * u + 3] = fmaf(a.w, wv, acc1[4 * u + 3]);
        }
    }
    {
        const float bias = qb1[c];
        #pragma unroll
        for (int i = 0; i < R2; i++)
            S->q1T[c * CLD + i] = fmaxf(acc1[i] + bias, 0.f);
    }
    __syncthreads();

    // ---- q2 = relu(q1 @ qw2 + qb2) ----
    float acc2[R2];
    #pragma unroll
    for (int i = 0; i < R2; i++) acc2[i] = 0.f;
    #pragma unroll 4
    for (int k = 0; k < H; k++) {
        const float wv = qw2[k * H + c];
        const float4* row = (const float4*)(S->q1T + k * CLD);
        #pragma unroll
        for (int u = 0; u < 8; u++) {
            float4 a = row[u];
            acc2[4 * u + 0] = fmaf(a.x, wv, acc2[4 * u + 0]);
            acc2[4 * u + 1] = fmaf(a.y, wv, acc2[4 * u + 1]);
            acc2[4 * u + 2] = fmaf(a.z, wv, acc2[4 * u + 2]);
            acc2[4 * u + 3] = fmaf(a.w, wv, acc2[4 * u + 3]);
        }
    }

    // ---- q3: reduce over channels ----
    {
        const float qb2c = qb2[c], qw3c = qw3[c];
        float part[R2];
        #pragma unroll
        for (int i = 0; i < R2; i++)
            part[i] = fmaxf(acc2[i] + qb2c, 0.f) * qw3c;
        #pragma unroll
        for (int o = 16; o > 0; o >>= 1) {
            #pragma unroll
            for (int i = 0; i < R2; i++)
                part[i] += __shfl_xor_sync(0xffffffffu, part[i], o);
        }
        if (lane == 0) {
            #pragma unroll
            for (int i = 0; i < R2; i++)
                S->wpart[w * R2 + i] = part[i];
        }
    }
    __syncthreads();
    if (t < R2) {
        float s = qb3[0];
        #pragma unroll
        for (int wi = 0; wi < 8; wi++) s += S->wpart[wi * R2 + t];
        out[rb + t] = s;
    }
}

extern "C" void kernel_launch(void* const* d_in, const int* in_sizes, int n_in,
                              void* d_out, int out_size)
{
    const float* obs       = (const float*)d_in[0];
    const float* obstacles = (const float*)d_in[1];
    const float* act       = (const float*)d_in[2];
    const float* ow1       = (const float*)d_in[3];
    const float* ob1       = (const float*)d_in[4];
    const float* ow2       = (const float*)d_in[5];
    const float* ob2       = (const float*)d_in[6];
    const float* qw1       = (const float*)d_in[7];
    const float* qb1       = (const float*)d_in[8];
    const float* qw2       = (const float*)d_in[9];
    const float* qb2       = (const float*)d_in[10];
    const float* qw3       = (const float*)d_in[11];
    const float* qb3       = (const float*)d_in[12];
    float* out             = (float*)d_out;

    cudaFuncSetAttribute(setq_enc,
                         cudaFuncAttributeMaxDynamicSharedMemorySize, (int)sizeof(EncSmem));
    cudaFuncSetAttribute(setq_qhead,
                         cudaFuncAttributeMaxDynamicSharedMemorySize, (int)sizeof(QSmem));

    prep_ow2<<<dim3(8, 8), dim3(32, 8)>>>(ow2);
    setq_enc<<<BATCH, 512, sizeof(EncSmem)>>>(obs, obstacles, ow1, ob1, ob2);
    setq_qhead<<<BATCH / R2, 256, sizeof(QSmem)>>>(obs, act, qw1, qb1,
                                                   qw2, qb2, qw3, qb3, out);
}